// round 1
// baseline (speedup 1.0000x reference)
#include <cuda_runtime.h>
#include <math.h>

#define Bq 4096
#define Dq 1024

__device__ __constant__ float c_dummy; // none needed; constants below

static __device__ float g_zni[Bq * Dq];           // 16 MB  normalized zis
static __device__ float g_znj[Bq * Dq];           // 16 MB  normalized zjs
static __device__ float g_sim[(size_t)Bq * Bq];   // 64 MB  similarity matrix
static __device__ float g_iloss[Bq];
static __device__ float g_tloss[Bq];

#define TEMP_INV 10.0f
#define GAMMA_F  0.8f
#define ALPHA_F  0.5f
#define EPS_F    1e-14f

// ---------------------------------------------------------------------------
// K1: row L2-normalize. 2*Bq blocks; block b < Bq -> zis row b, else zjs row.
// ---------------------------------------------------------------------------
__global__ void __launch_bounds__(256) k_normalize(const float* __restrict__ zis,
                                                   const float* __restrict__ zjs) {
    int bid = blockIdx.x;
    int t = threadIdx.x;
    const float* src;
    float* dst;
    if (bid < Bq) { src = zis + (size_t)bid * Dq; dst = g_zni + (size_t)bid * Dq; }
    else          { src = zjs + (size_t)(bid - Bq) * Dq; dst = g_znj + (size_t)(bid - Bq) * Dq; }

    float4 v = ((const float4*)src)[t];                 // 256 threads * 4 = 1024
    float ss = v.x * v.x + v.y * v.y + v.z * v.z + v.w * v.w;

    __shared__ float red[256];
    red[t] = ss;
    __syncthreads();
    #pragma unroll
    for (int s = 128; s > 0; s >>= 1) {
        if (t < s) red[t] += red[t + s];
        __syncthreads();
    }
    float scale = 1.0f / sqrtf(red[0]);
    float4 o = make_float4(v.x * scale, v.y * scale, v.z * scale, v.w * scale);
    ((float4*)dst)[t] = o;
}

// ---------------------------------------------------------------------------
// K2: sim = Zi_n @ Zj_n^T  (NT GEMM, fp32).
// 128x128 block tile, BK=16, 256 threads, 8x8 microtile per thread.
// ---------------------------------------------------------------------------
#define BM 128
#define BN 128
#define BK 16

__global__ void __launch_bounds__(256) k_gemm() {
    __shared__ float As[BK][BM + 4];   // +4 pad: bank spread, 16B-aligned rows
    __shared__ float Bs[BK][BN + 4];

    int t = threadIdx.x;
    int tx = t & 15;       // 0..15 -> N direction
    int ty = t >> 4;       // 0..15 -> M direction
    int bx = blockIdx.x;   // N tile
    int by = blockIdx.y;   // M tile

    const float* Abase = g_zni + (size_t)by * BM * Dq;
    const float* Bbase = g_znj + (size_t)bx * BN * Dq;

    float acc[8][8];
    #pragma unroll
    for (int i = 0; i < 8; i++)
        #pragma unroll
        for (int j = 0; j < 8; j++) acc[i][j] = 0.0f;

    for (int kt = 0; kt < Dq; kt += BK) {
        // Load A/B tiles: 128 rows x 16 k each = 512 float4 per operand.
        #pragma unroll
        for (int l = 0; l < 2; l++) {
            int idx = t + l * 256;
            int m  = idx >> 2;            // row within tile
            int k4 = (idx & 3) << 2;      // k offset (0,4,8,12)
            float4 va = *(const float4*)(Abase + (size_t)m * Dq + kt + k4);
            As[k4 + 0][m] = va.x; As[k4 + 1][m] = va.y;
            As[k4 + 2][m] = va.z; As[k4 + 3][m] = va.w;
            float4 vb = *(const float4*)(Bbase + (size_t)m * Dq + kt + k4);
            Bs[k4 + 0][m] = vb.x; Bs[k4 + 1][m] = vb.y;
            Bs[k4 + 2][m] = vb.z; Bs[k4 + 3][m] = vb.w;
        }
        __syncthreads();

        #pragma unroll
        for (int k = 0; k < BK; k++) {
            float a[8], b[8];
            *(float4*)(a)     = *(const float4*)&As[k][ty * 8];
            *(float4*)(a + 4) = *(const float4*)&As[k][ty * 8 + 4];
            *(float4*)(b)     = *(const float4*)&Bs[k][tx * 8];
            *(float4*)(b + 4) = *(const float4*)&Bs[k][tx * 8 + 4];
            #pragma unroll
            for (int i = 0; i < 8; i++)
                #pragma unroll
                for (int j = 0; j < 8; j++)
                    acc[i][j] = fmaf(a[i], b[j], acc[i][j]);
        }
        __syncthreads();
    }

    int row0 = by * BM + ty * 8;
    int col0 = bx * BN + tx * 8;
    #pragma unroll
    for (int i = 0; i < 8; i++) {
        float4 o0 = make_float4(acc[i][0], acc[i][1], acc[i][2], acc[i][3]);
        float4 o1 = make_float4(acc[i][4], acc[i][5], acc[i][6], acc[i][7]);
        *(float4*)&g_sim[(size_t)(row0 + i) * Bq + col0]     = o0;
        *(float4*)&g_sim[(size_t)(row0 + i) * Bq + col0 + 4] = o1;
    }
}

// ---------------------------------------------------------------------------
// K3: image (row) pass. One block per row i. Row cached in smem (16 KB).
// pass1: rowmax of idd; pass2: sum exp, sum exp*diff (excluding diagonal).
// ---------------------------------------------------------------------------
__global__ void __launch_bounds__(256) k_image(const float* __restrict__ sI,
                                               const float* __restrict__ bI,
                                               const int* __restrict__ ids) {
    int i = blockIdx.x;
    int t = threadIdx.x;
    __shared__ float srow[Bq];
    __shared__ float red[256];
    __shared__ float red2[256];

    const float* simrow = g_sim + (size_t)i * Bq;
    for (int j = t; j < Bq; j += 256) srow[j] = simrow[j];
    __syncthreads();

    float diag = srow[i];

    // pass 1: max over the full row (diagonal contributes 0, matching reference)
    float m = -1e30f;
    for (int j = t; j < Bq; j += 256) {
        float v = (srow[j] - diag) * TEMP_INV;
        m = fmaxf(m, v);
    }
    red[t] = m;
    __syncthreads();
    #pragma unroll
    for (int s = 128; s > 0; s >>= 1) {
        if (t < s) red[t] = fmaxf(red[t], red[t + s]);
        __syncthreads();
    }
    int id = ids[i];
    float old_b = bI[id];
    float new_b = fmaxf(red[0], old_b);
    __syncthreads();

    // pass 2
    float se = 0.0f, sed = 0.0f;
    for (int j = t; j < Bq; j += 256) {
        if (j == i) continue;
        float d = srow[j] - diag;
        float e = expf(d * TEMP_INV - new_b);
        se += e;
        sed += e * d;
    }
    red[t] = se;
    red2[t] = sed;
    __syncthreads();
    #pragma unroll
    for (int s = 128; s > 0; s >>= 1) {
        if (t < s) { red[t] += red[t + s]; red2[t] += red2[t + s]; }
        __syncthreads();
    }
    if (t == 0) {
        float g = red[0] / (float)(Bq - 1);
        float s_new = (1.0f - GAMMA_F) * sI[id] * expf(old_b - new_b) + GAMMA_F * g;
        float s_c = fmaxf(s_new, EPS_F);
        g_iloss[i] = red2[0] / s_c / (float)(Bq - 1);
    }
}

// ---------------------------------------------------------------------------
// K4: text (column) pass. Each block handles 32 columns; 256 threads =
// 8 rows x 32 cols per iteration -> coalesced row-segment reads (L2 hits,
// sim fits in L2). Two passes: colmax, then sums.
// ---------------------------------------------------------------------------
__global__ void __launch_bounds__(256) k_text(const float* __restrict__ sT,
                                              const float* __restrict__ bT,
                                              const int* __restrict__ ids) {
    const int TC = 32, TR = 8;
    int tx = threadIdx.x & (TC - 1);
    int ty = threadIdx.x / TC;
    int col = blockIdx.x * TC + tx;

    float diag = g_sim[(size_t)col * Bq + col];
    int id = ids[col];
    float old_b = bT[id];

    // pass 1: column max of tdd
    float m = -1e30f;
    for (int r = ty; r < Bq; r += TR) {
        float v = g_sim[(size_t)r * Bq + col];
        m = fmaxf(m, (v - diag) * TEMP_INV);
    }
    __shared__ float red[8][32];
    red[ty][tx] = m;
    __syncthreads();
    if (ty == 0) {
        float mm = red[0][tx];
        #pragma unroll
        for (int q = 1; q < 8; q++) mm = fmaxf(mm, red[q][tx]);
        red[0][tx] = fmaxf(mm, old_b);
    }
    __syncthreads();
    float new_b = red[0][tx];
    __syncthreads();

    // pass 2
    float se = 0.0f, sed = 0.0f;
    for (int r = ty; r < Bq; r += TR) {
        if (r == col) continue;
        float d = g_sim[(size_t)r * Bq + col] - diag;
        float e = expf(d * TEMP_INV - new_b);
        se += e;
        sed += e * d;
    }
    __shared__ float redA[8][32];
    __shared__ float redB[8][32];
    redA[ty][tx] = se;
    redB[ty][tx] = sed;
    __syncthreads();
    if (ty == 0) {
        float a = 0.0f, b2 = 0.0f;
        #pragma unroll
        for (int q = 0; q < 8; q++) { a += redA[q][tx]; b2 += redB[q][tx]; }
        float g = a / (float)(Bq - 1);
        float s_new = (1.0f - GAMMA_F) * sT[id] * expf(old_b - new_b) + GAMMA_F * g;
        float s_c = fmaxf(s_new, EPS_F);
        g_tloss[col] = b2 / s_c / (float)(Bq - 1);
    }
}

// ---------------------------------------------------------------------------
// K5: final scalar reduction.
// ---------------------------------------------------------------------------
__global__ void __launch_bounds__(256) k_final(float* __restrict__ out) {
    int t = threadIdx.x;
    float si = 0.0f, st = 0.0f;
    for (int i = t; i < Bq; i += 256) {
        si += g_iloss[i];
        st += g_tloss[i];
    }
    __shared__ float rI[256];
    __shared__ float rT[256];
    rI[t] = si;
    rT[t] = st;
    __syncthreads();
    #pragma unroll
    for (int s = 128; s > 0; s >>= 1) {
        if (t < s) { rI[t] += rI[t + s]; rT[t] += rT[t + s]; }
        __syncthreads();
    }
    if (t == 0) {
        float image_mean = rI[0] / (float)Bq;
        float text_mean  = rT[0] / (float)Bq;
        out[0] = ALPHA_F * image_mean + (1.0f - ALPHA_F) * text_mean;
    }
}

// ---------------------------------------------------------------------------
// kernel_launch: inputs per metadata order:
//  0: zis [B*D] f32, 1: zjs [B*D] f32, 2: s_I [N] f32, 3: s_T [N] f32,
//  4: b_I [N] f32, 5: b_T [N] f32, 6: ids [B] i32. out: 1 float.
// ---------------------------------------------------------------------------
extern "C" void kernel_launch(void* const* d_in, const int* in_sizes, int n_in,
                              void* d_out, int out_size) {
    const float* zis = (const float*)d_in[0];
    const float* zjs = (const float*)d_in[1];
    const float* s_I = (const float*)d_in[2];
    const float* s_T = (const float*)d_in[3];
    const float* b_I = (const float*)d_in[4];
    const float* b_T = (const float*)d_in[5];
    const int*   ids = (const int*)d_in[6];

    k_normalize<<<2 * Bq, 256>>>(zis, zjs);
    dim3 g(Bq / BN, Bq / BM);
    k_gemm<<<g, 256>>>();
    k_image<<<Bq, 256>>>(s_I, b_I, ids);
    k_text<<<Bq / 32, 256>>>(s_T, b_T, ids);
    k_final<<<1, 256>>>((float*)d_out);
}

// round 4
// speedup vs baseline: 4.5319x; 4.5319x over previous
#include <cuda_runtime.h>
#include <cuda_fp16.h>
#include <math.h>
#include <stdint.h>

#define Bq 4096
#define Dq 1024

#define TEMP_INV 10.0f
#define GAMMA_F  0.8f
#define ALPHA_F  0.5f
#define EPS_F    1e-14f

static __device__ __align__(16) __half g_Ah[(size_t)Bq * Dq];   // 8 MB
static __device__ __align__(16) __half g_Bh[(size_t)Bq * Dq];   // 8 MB
static __device__ float g_sim[(size_t)Bq * Bq];                 // 64 MB
static __device__ float g_iloss[Bq];
static __device__ float g_tloss[Bq];

// ---------------------------------------------------------------------------
// helpers
// ---------------------------------------------------------------------------
__device__ __forceinline__ uint32_t smem_u32(const void* p) {
    uint32_t a;
    asm("{ .reg .u64 t; cvta.to.shared.u64 t, %1; cvt.u32.u64 %0, t; }" : "=r"(a) : "l"(p));
    return a;
}
#define SWZ(off) ((off) ^ (((off) >> 3) & 0x70))

__device__ __forceinline__ void cpa16(uint32_t s, const void* g) {
    asm volatile("cp.async.cg.shared.global [%0], [%1], 16;" :: "r"(s), "l"(g));
}
template <int N>
__device__ __forceinline__ void cpwait() {
    asm volatile("cp.async.wait_group %0;" :: "n"(N) : "memory");
}

__device__ __forceinline__ void ldsm4(uint32_t* r, uint32_t addr) {
    asm volatile("ldmatrix.sync.aligned.m8n8.x4.shared.b16 {%0,%1,%2,%3}, [%4];"
                 : "=r"(r[0]), "=r"(r[1]), "=r"(r[2]), "=r"(r[3]) : "r"(addr));
}
__device__ __forceinline__ void mma16816(float* d, const uint32_t* a, const uint32_t* b) {
    asm volatile(
        "mma.sync.aligned.m16n8k16.row.col.f32.f16.f16.f32 "
        "{%0,%1,%2,%3}, {%4,%5,%6,%7}, {%8,%9}, {%0,%1,%2,%3};"
        : "+f"(d[0]), "+f"(d[1]), "+f"(d[2]), "+f"(d[3])
        : "r"(a[0]), "r"(a[1]), "r"(a[2]), "r"(a[3]), "r"(b[0]), "r"(b[1]));
}

// ---------------------------------------------------------------------------
// K1: row L2-normalize + fp16 convert.
// ---------------------------------------------------------------------------
__global__ void __launch_bounds__(256) k_prep(const float* __restrict__ zis,
                                              const float* __restrict__ zjs) {
    int bid = blockIdx.x;
    int t = threadIdx.x;
    bool isA = bid < Bq;
    size_t row = isA ? bid : bid - Bq;
    const float* src = (isA ? zis : zjs) + row * Dq;
    __half* dst = (isA ? g_Ah : g_Bh) + row * Dq;

    float4 v = ((const float4*)src)[t];
    float ss = v.x * v.x + v.y * v.y + v.z * v.z + v.w * v.w;

    __shared__ float red[256];
    red[t] = ss;
    __syncthreads();
    #pragma unroll
    for (int s = 128; s > 0; s >>= 1) {
        if (t < s) red[t] += red[t + s];
        __syncthreads();
    }
    float scale = 1.0f / sqrtf(red[0]);

    __half2 h01, h23;
    h01 = __floats2half2_rn(v.x * scale, v.y * scale);
    h23 = __floats2half2_rn(v.z * scale, v.w * scale);
    *(__half2*)&dst[t * 4]     = h01;
    *(__half2*)&dst[t * 4 + 2] = h23;
}

// ---------------------------------------------------------------------------
// K2: fp16 mma.sync GEMM. sim = A @ B^T.
// CTA tile 128x128, BK=64, 3-stage cp.async, 8 warps (2M x 4N), warp 64x32.
// ---------------------------------------------------------------------------
#define GM 128
#define GN 128
#define GK 64
#define NCH (Dq / GK)          // 16
#define ATILE (GM * 128)       // 16 KB
#define BTILE (GN * 128)       // 16 KB
#define STGB (ATILE + BTILE)   // 32 KB
#define NSTG 3
#define GSMEM (NSTG * STGB)    // 96 KB

__global__ void __launch_bounds__(256) k_gemm_mma() {
    extern __shared__ char sm[];
    uint32_t sbase = smem_u32(sm);
    int t = threadIdx.x;
    int wid = t >> 5, lane = t & 31;
    int wm = wid & 1;        // 0..1 -> M offset 64*wm
    int wn = wid >> 1;       // 0..3 -> N offset 32*wn
    int by = blockIdx.y, bx = blockIdx.x;

    const char* Ag = (const char*)(g_Ah + (size_t)(by * GM) * Dq);
    const char* Bg = (const char*)(g_Bh + (size_t)(bx * GN) * Dq);

    float acc[4][4][4];
    #pragma unroll
    for (int i = 0; i < 4; i++)
        #pragma unroll
        for (int j = 0; j < 4; j++)
            #pragma unroll
            for (int q = 0; q < 4; q++) acc[i][j][q] = 0.0f;

    int row_ld = t >> 3;   // 0..31
    int seg = t & 7;       // 16B granule

    // issue chunk c into stage c%NSTG
    #define ISSUE(c)                                                          \
    do {                                                                      \
        int _s = (c) % NSTG;                                                  \
        uint32_t _sA = sbase + _s * STGB;                                     \
        uint32_t _sB = _sA + ATILE;                                           \
        size_t _ko = (size_t)(c) * 128 + seg * 16;                            \
        _Pragma("unroll")                                                     \
        for (int _j = 0; _j < 4; _j++) {                                      \
            int _r = row_ld + 32 * _j;                                        \
            uint32_t _so = SWZ((uint32_t)(_r * 128 + seg * 16));              \
            cpa16(_sA + _so, Ag + (size_t)_r * (Dq * 2) + _ko);               \
            cpa16(_sB + _so, Bg + (size_t)_r * (Dq * 2) + _ko);               \
        }                                                                     \
        asm volatile("cp.async.commit_group;" ::: "memory");                  \
    } while (0)

    ISSUE(0);
    ISSUE(1);

    for (int c = 0; c < NCH; c++) {
        if (c < NCH - 2) cpwait<1>(); else cpwait<0>();
        __syncthreads();               // data visible + all warps done with stage being overwritten
        if (c + 2 < NCH) ISSUE(c + 2);

        int s = c % NSTG;
        uint32_t sA = sbase + s * STGB;
        uint32_t sB = sA + ATILE;
        #pragma unroll
        for (int ks = 0; ks < 4; ks++) {
            uint32_t a[4][4];
            #pragma unroll
            for (int mt = 0; mt < 4; mt++) {
                int r = wm * 64 + mt * 16 + (lane & 15);
                ldsm4(a[mt], sA + SWZ((uint32_t)(r * 128 + ks * 32 + ((lane >> 4) << 4))));
            }
            uint32_t b[2][4];
            #pragma unroll
            for (int h = 0; h < 2; h++) {
                int nr = wn * 32 + h * 16 + ((lane >> 4) << 3) + (lane & 7);
                ldsm4(b[h], sB + SWZ((uint32_t)(nr * 128 + ks * 32 + (((lane >> 3) & 1) << 4))));
            }
            #pragma unroll
            for (int mt = 0; mt < 4; mt++)
                #pragma unroll
                for (int nt = 0; nt < 4; nt++)
                    mma16816(acc[mt][nt], a[mt], &b[nt >> 1][(nt & 1) * 2]);
        }
    }

    // epilogue: direct stores (no smem reuse, no sync needed)
    int r0 = by * GM + wm * 64 + (lane >> 2);
    int c0 = bx * GN + wn * 32 + 2 * (lane & 3);
    #pragma unroll
    for (int mt = 0; mt < 4; mt++) {
        #pragma unroll
        for (int nt = 0; nt < 4; nt++) {
            float* p0 = g_sim + (size_t)(r0 + mt * 16) * Bq + c0 + nt * 8;
            float* p1 = g_sim + (size_t)(r0 + mt * 16 + 8) * Bq + c0 + nt * 8;
            *(float2*)p0 = make_float2(acc[mt][nt][0], acc[mt][nt][1]);
            *(float2*)p1 = make_float2(acc[mt][nt][2], acc[mt][nt][3]);
        }
    }
}

// ---------------------------------------------------------------------------
// K3: image (row) pass. One block per row.
// ---------------------------------------------------------------------------
__global__ void __launch_bounds__(256) k_image(const float* __restrict__ sI,
                                               const float* __restrict__ bI,
                                               const int* __restrict__ ids) {
    int i = blockIdx.x;
    int t = threadIdx.x;
    __shared__ float srow[Bq];
    __shared__ float red[256];
    __shared__ float red2[256];

    const float* simrow = g_sim + (size_t)i * Bq;
    for (int j = t; j < Bq; j += 256) srow[j] = simrow[j];
    __syncthreads();

    float diag = srow[i];
    float m = -1e30f;
    for (int j = t; j < Bq; j += 256)
        m = fmaxf(m, (srow[j] - diag) * TEMP_INV);
    red[t] = m;
    __syncthreads();
    #pragma unroll
    for (int s = 128; s > 0; s >>= 1) {
        if (t < s) red[t] = fmaxf(red[t], red[t + s]);
        __syncthreads();
    }
    int id = ids[i];
    float old_b = bI[id];
    float new_b = fmaxf(red[0], old_b);
    __syncthreads();

    float se = 0.0f, sed = 0.0f;
    for (int j = t; j < Bq; j += 256) {
        if (j == i) continue;
        float d = srow[j] - diag;
        float e = expf(d * TEMP_INV - new_b);
        se += e;
        sed += e * d;
    }
    red[t] = se;
    red2[t] = sed;
    __syncthreads();
    #pragma unroll
    for (int s = 128; s > 0; s >>= 1) {
        if (t < s) { red[t] += red[t + s]; red2[t] += red2[t + s]; }
        __syncthreads();
    }
    if (t == 0) {
        float g = red[0] / (float)(Bq - 1);
        float s_new = (1.0f - GAMMA_F) * sI[id] * expf(old_b - new_b) + GAMMA_F * g;
        float s_c = fmaxf(s_new, EPS_F);
        g_iloss[i] = red2[0] / s_c / (float)(Bq - 1);
    }
}

// ---------------------------------------------------------------------------
// K4: text (column) pass. 1024 threads = 32 rows x 32 cols.
// ---------------------------------------------------------------------------
__global__ void __launch_bounds__(1024) k_text(const float* __restrict__ sT,
                                               const float* __restrict__ bT,
                                               const int* __restrict__ ids) {
    int tx = threadIdx.x & 31;
    int ty = threadIdx.x >> 5;
    int col = blockIdx.x * 32 + tx;

    float diag = g_sim[(size_t)col * Bq + col];
    int id = ids[col];
    float old_b = bT[id];

    float m = -1e30f;
    for (int r = ty; r < Bq; r += 32)
        m = fmaxf(m, (g_sim[(size_t)r * Bq + col] - diag) * TEMP_INV);

    __shared__ float redM[32][33];
    redM[ty][tx] = m;
    __syncthreads();
    if (ty == 0) {
        float mm = redM[0][tx];
        #pragma unroll
        for (int q = 1; q < 32; q++) mm = fmaxf(mm, redM[q][tx]);
        redM[0][tx] = fmaxf(mm, old_b);
    }
    __syncthreads();
    float new_b = redM[0][tx];
    __syncthreads();

    float se = 0.0f, sed = 0.0f;
    for (int r = ty; r < Bq; r += 32) {
        if (r == col) continue;
        float d = g_sim[(size_t)r * Bq + col] - diag;
        float e = expf(d * TEMP_INV - new_b);
        se += e;
        sed += e * d;
    }
    __shared__ float redA[32][33];
    __shared__ float redB[32][33];
    redA[ty][tx] = se;
    redB[ty][tx] = sed;
    __syncthreads();
    if (ty == 0) {
        float a = 0.0f, b2 = 0.0f;
        #pragma unroll
        for (int q = 0; q < 32; q++) { a += redA[q][tx]; b2 += redB[q][tx]; }
        float g = a / (float)(Bq - 1);
        float s_new = (1.0f - GAMMA_F) * sT[id] * expf(old_b - new_b) + GAMMA_F * g;
        float s_c = fmaxf(s_new, EPS_F);
        g_tloss[col] = b2 / s_c / (float)(Bq - 1);
    }
}

// ---------------------------------------------------------------------------
// K5: final scalar reduction.
// ---------------------------------------------------------------------------
__global__ void __launch_bounds__(256) k_final(float* __restrict__ out) {
    int t = threadIdx.x;
    float si = 0.0f, st = 0.0f;
    for (int i = t; i < Bq; i += 256) { si += g_iloss[i]; st += g_tloss[i]; }
    __shared__ float rI[256];
    __shared__ float rT[256];
    rI[t] = si; rT[t] = st;
    __syncthreads();
    #pragma unroll
    for (int s = 128; s > 0; s >>= 1) {
        if (t < s) { rI[t] += rI[t + s]; rT[t] += rT[t + s]; }
        __syncthreads();
    }
    if (t == 0)
        out[0] = ALPHA_F * (rI[0] / (float)Bq) + (1.0f - ALPHA_F) * (rT[0] / (float)Bq);
}

// ---------------------------------------------------------------------------
extern "C" void kernel_launch(void* const* d_in, const int* in_sizes, int n_in,
                              void* d_out, int out_size) {
    const float* zis = (const float*)d_in[0];
    const float* zjs = (const float*)d_in[1];
    const float* s_I = (const float*)d_in[2];
    const float* s_T = (const float*)d_in[3];
    const float* b_I = (const float*)d_in[4];
    const float* b_T = (const float*)d_in[5];
    const int*   ids = (const int*)d_in[6];

    cudaFuncSetAttribute(k_gemm_mma, cudaFuncAttributeMaxDynamicSharedMemorySize, GSMEM);

    k_prep<<<2 * Bq, 256>>>(zis, zjs);
    dim3 g(Bq / GN, Bq / GM);
    k_gemm_mma<<<g, 256, GSMEM>>>();
    k_image<<<Bq, 256>>>(s_I, b_I, ids);
    k_text<<<Bq / 32, 1024>>>(s_T, b_T, ids);
    k_final<<<1, 256>>>((float*)d_out);
}

// round 5
// speedup vs baseline: 6.9680x; 1.5375x over previous
#include <cuda_runtime.h>
#include <cuda_fp16.h>
#include <math.h>
#include <stdint.h>

#define Bq 4096
#define Dq 1024

#define TEMP_INV 10.0f
#define GAMMA_F  0.8f
#define ALPHA_F  0.5f
#define EPS_F    1e-14f

static __device__ __align__(16) __half g_Ah[(size_t)Bq * Dq];   // 8 MB
static __device__ __align__(16) __half g_Bh[(size_t)Bq * Dq];   // 8 MB

// per-row / per-col sufficient statistics of sim (e = exp(10*sim))
static __device__ float g_rS1[Bq];   // row: sum e
static __device__ float g_rS2[Bq];   // row: sum e*sim
static __device__ int   g_rM [Bq];   // row: max sim (biased +4, int-ordered)
static __device__ float g_cS1[Bq];
static __device__ float g_cS2[Bq];
static __device__ int   g_cM [Bq];
static __device__ float g_diag[Bq];

// ---------------------------------------------------------------------------
// helpers
// ---------------------------------------------------------------------------
__device__ __forceinline__ uint32_t smem_u32(const void* p) {
    uint32_t a;
    asm("{ .reg .u64 t; cvta.to.shared.u64 t, %1; cvt.u32.u64 %0, t; }" : "=r"(a) : "l"(p));
    return a;
}
#define SWZ(off) ((off) ^ (((off) >> 3) & 0x70))

__device__ __forceinline__ void cpa16(uint32_t s, const void* g) {
    asm volatile("cp.async.cg.shared.global [%0], [%1], 16;" :: "r"(s), "l"(g));
}
template <int N>
__device__ __forceinline__ void cpwait() {
    asm volatile("cp.async.wait_group %0;" :: "n"(N) : "memory");
}
__device__ __forceinline__ void ldsm4(uint32_t* r, uint32_t addr) {
    asm volatile("ldmatrix.sync.aligned.m8n8.x4.shared.b16 {%0,%1,%2,%3}, [%4];"
                 : "=r"(r[0]), "=r"(r[1]), "=r"(r[2]), "=r"(r[3]) : "r"(addr));
}
__device__ __forceinline__ void mma16816(float* d, const uint32_t* a, const uint32_t* b) {
    asm volatile(
        "mma.sync.aligned.m16n8k16.row.col.f32.f16.f16.f32 "
        "{%0,%1,%2,%3}, {%4,%5,%6,%7}, {%8,%9}, {%0,%1,%2,%3};"
        : "+f"(d[0]), "+f"(d[1]), "+f"(d[2]), "+f"(d[3])
        : "r"(a[0]), "r"(a[1]), "r"(a[2]), "r"(a[3]), "r"(b[0]), "r"(b[1]));
}

// ---------------------------------------------------------------------------
// K0: zero the global accumulators (graph replays need a clean slate).
// ---------------------------------------------------------------------------
__global__ void __launch_bounds__(256) k_zero() {
    int i = blockIdx.x * 256 + threadIdx.x;
    if (i < Bq) {
        g_rS1[i] = 0.0f; g_rS2[i] = 0.0f; g_rM[i] = 0;
        g_cS1[i] = 0.0f; g_cS2[i] = 0.0f; g_cM[i] = 0;
    }
}

// ---------------------------------------------------------------------------
// K1: row L2-normalize + fp16 convert.
// ---------------------------------------------------------------------------
__global__ void __launch_bounds__(256) k_prep(const float* __restrict__ zis,
                                              const float* __restrict__ zjs) {
    int bid = blockIdx.x;
    int t = threadIdx.x;
    bool isA = bid < Bq;
    size_t row = isA ? bid : bid - Bq;
    const float* src = (isA ? zis : zjs) + row * Dq;
    __half* dst = (isA ? g_Ah : g_Bh) + row * Dq;

    float4 v = ((const float4*)src)[t];
    float ss = v.x * v.x + v.y * v.y + v.z * v.z + v.w * v.w;

    __shared__ float red[256];
    red[t] = ss;
    __syncthreads();
    #pragma unroll
    for (int s = 128; s > 0; s >>= 1) {
        if (t < s) red[t] += red[t + s];
        __syncthreads();
    }
    float scale = 1.0f / sqrtf(red[0]);

    __half2 h01 = __floats2half2_rn(v.x * scale, v.y * scale);
    __half2 h23 = __floats2half2_rn(v.z * scale, v.w * scale);
    *(__half2*)&dst[t * 4]     = h01;
    *(__half2*)&dst[t * 4 + 2] = h23;
}

// ---------------------------------------------------------------------------
// K2: fp16 mma.sync GEMM with FUSED statistics epilogue (sim never stored).
// CTA 128x128, BK=64, 3-stage cp.async, 8 warps (2M x 4N), warp 64x32.
// ---------------------------------------------------------------------------
#define GM 128
#define GN 128
#define NCH (Dq / 64)          // 16
#define ATILE (GM * 128)       // 16 KB
#define BTILE (GN * 128)       // 16 KB
#define STGB (ATILE + BTILE)   // 32 KB
#define NSTG 3
#define GSMEM (NSTG * STGB)    // 96 KB

__global__ void __launch_bounds__(256) k_gemm_fused() {
    extern __shared__ char sm[];
    uint32_t sbase = smem_u32(sm);
    int t = threadIdx.x;
    int wid = t >> 5, lane = t & 31;
    int wm = wid & 1;        // M offset 64*wm
    int wn = wid >> 1;       // N offset 32*wn
    int by = blockIdx.y, bx = blockIdx.x;

    const char* Ag = (const char*)(g_Ah + (size_t)(by * GM) * Dq);
    const char* Bg = (const char*)(g_Bh + (size_t)(bx * GN) * Dq);

    float acc[4][4][4];
    #pragma unroll
    for (int i = 0; i < 4; i++)
        #pragma unroll
        for (int j = 0; j < 4; j++)
            #pragma unroll
            for (int q = 0; q < 4; q++) acc[i][j][q] = 0.0f;

    int row_ld = t >> 3;
    int seg = t & 7;

    #define ISSUE(c)                                                          \
    do {                                                                      \
        int _s = (c) % NSTG;                                                  \
        uint32_t _sA = sbase + _s * STGB;                                     \
        uint32_t _sB = _sA + ATILE;                                           \
        size_t _ko = (size_t)(c) * 128 + seg * 16;                            \
        _Pragma("unroll")                                                     \
        for (int _j = 0; _j < 4; _j++) {                                      \
            int _r = row_ld + 32 * _j;                                        \
            uint32_t _so = SWZ((uint32_t)(_r * 128 + seg * 16));              \
            cpa16(_sA + _so, Ag + (size_t)_r * (Dq * 2) + _ko);               \
            cpa16(_sB + _so, Bg + (size_t)_r * (Dq * 2) + _ko);               \
        }                                                                     \
        asm volatile("cp.async.commit_group;" ::: "memory");                  \
    } while (0)

    ISSUE(0);
    ISSUE(1);

    for (int c = 0; c < NCH; c++) {
        if (c < NCH - 2) cpwait<1>(); else cpwait<0>();
        __syncthreads();
        if (c + 2 < NCH) ISSUE(c + 2);

        int s = c % NSTG;
        uint32_t sA = sbase + s * STGB;
        uint32_t sB = sA + ATILE;
        #pragma unroll
        for (int ks = 0; ks < 4; ks++) {
            uint32_t a[4][4];
            #pragma unroll
            for (int mt = 0; mt < 4; mt++) {
                int r = wm * 64 + mt * 16 + (lane & 15);
                ldsm4(a[mt], sA + SWZ((uint32_t)(r * 128 + ks * 32 + ((lane >> 4) << 4))));
            }
            uint32_t b[2][4];
            #pragma unroll
            for (int h = 0; h < 2; h++) {
                int nr = wn * 32 + h * 16 + ((lane >> 4) << 3) + (lane & 7);
                ldsm4(b[h], sB + SWZ((uint32_t)(nr * 128 + ks * 32 + (((lane >> 3) & 1) << 4))));
            }
            #pragma unroll
            for (int mt = 0; mt < 4; mt++)
                #pragma unroll
                for (int nt = 0; nt < 4; nt++)
                    mma16816(acc[mt][nt], a[mt], &b[nt >> 1][(nt & 1) * 2]);
        }
    }

    // ---------------- fused statistics epilogue ----------------
    __syncthreads();   // mainloop smem dead; reuse for reductions
    float* sred = (float*)sm;
    float* rS1 = sred;         float* rS2 = sred + 128;  int* rMx = (int*)(sred + 256);
    float* cS1 = sred + 384;   float* cS2 = sred + 512;  int* cMx = (int*)(sred + 640);
    if (t < 128) {
        rS1[t] = 0.0f; rS2[t] = 0.0f; rMx[t] = 0;
        cS1[t] = 0.0f; cS2[t] = 0.0f; cMx[t] = 0;
    }
    __syncthreads();

    float cs1[4][2], cs2[4][2], cmx[4][2];
    #pragma unroll
    for (int nt = 0; nt < 4; nt++)
        #pragma unroll
        for (int cc = 0; cc < 2; cc++) { cs1[nt][cc] = 0.0f; cs2[nt][cc] = 0.0f; cmx[nt][cc] = -1e30f; }

    #pragma unroll
    for (int mt = 0; mt < 4; mt++) {
        float s1A = 0.0f, s2A = 0.0f, mA = -1e30f;
        float s1B = 0.0f, s2B = 0.0f, mB = -1e30f;
        #pragma unroll
        for (int nt = 0; nt < 4; nt++) {
            float x0 = acc[mt][nt][0], x1 = acc[mt][nt][1];
            float x2 = acc[mt][nt][2], x3 = acc[mt][nt][3];
            float e0 = __expf(10.0f * x0), e1 = __expf(10.0f * x1);
            float e2 = __expf(10.0f * x2), e3 = __expf(10.0f * x3);
            s1A += e0 + e1;  s2A += fmaf(e0, x0, e1 * x1);  mA = fmaxf(mA, fmaxf(x0, x1));
            s1B += e2 + e3;  s2B += fmaf(e2, x2, e3 * x3);  mB = fmaxf(mB, fmaxf(x2, x3));
            cs1[nt][0] += e0 + e2;  cs2[nt][0] += fmaf(e0, x0, e2 * x2);
            cmx[nt][0] = fmaxf(cmx[nt][0], fmaxf(x0, x2));
            cs1[nt][1] += e1 + e3;  cs2[nt][1] += fmaf(e1, x1, e3 * x3);
            cmx[nt][1] = fmaxf(cmx[nt][1], fmaxf(x1, x3));
        }
        // reduce rows over the 4 lanes of a quad (lane&3 varies -> warp's 32 cols)
        #pragma unroll
        for (int d = 1; d < 4; d <<= 1) {
            s1A += __shfl_xor_sync(0xffffffffu, s1A, d);
            s2A += __shfl_xor_sync(0xffffffffu, s2A, d);
            mA = fmaxf(mA, __shfl_xor_sync(0xffffffffu, mA, d));
            s1B += __shfl_xor_sync(0xffffffffu, s1B, d);
            s2B += __shfl_xor_sync(0xffffffffu, s2B, d);
            mB = fmaxf(mB, __shfl_xor_sync(0xffffffffu, mB, d));
        }
        if ((lane & 3) == 0) {
            int rA = wm * 64 + mt * 16 + (lane >> 2);
            atomicAdd(&rS1[rA], s1A); atomicAdd(&rS2[rA], s2A);
            atomicMax(&rMx[rA], __float_as_int(mA + 4.0f));
            int rB = rA + 8;
            atomicAdd(&rS1[rB], s1B); atomicAdd(&rS2[rB], s2B);
            atomicMax(&rMx[rB], __float_as_int(mB + 4.0f));
        }
    }
    // reduce cols over the 8 lanes sharing lane&3 (lane>>2 varies -> warp's 64 rows)
    #pragma unroll
    for (int nt = 0; nt < 4; nt++)
        #pragma unroll
        for (int cc = 0; cc < 2; cc++) {
            #pragma unroll
            for (int d = 4; d < 32; d <<= 1) {
                cs1[nt][cc] += __shfl_xor_sync(0xffffffffu, cs1[nt][cc], d);
                cs2[nt][cc] += __shfl_xor_sync(0xffffffffu, cs2[nt][cc], d);
                cmx[nt][cc] = fmaxf(cmx[nt][cc], __shfl_xor_sync(0xffffffffu, cmx[nt][cc], d));
            }
        }
    if (lane < 4) {
        #pragma unroll
        for (int nt = 0; nt < 4; nt++)
            #pragma unroll
            for (int cc = 0; cc < 2; cc++) {
                int cg = wn * 32 + nt * 8 + 2 * lane + cc;
                atomicAdd(&cS1[cg], cs1[nt][cc]); atomicAdd(&cS2[cg], cs2[nt][cc]);
                atomicMax(&cMx[cg], __float_as_int(cmx[nt][cc] + 4.0f));
            }
    }
    // diagonal CTAs scatter diag values
    if (by == bx) {
        #pragma unroll
        for (int mt = 0; mt < 4; mt++)
            #pragma unroll
            for (int nt = 0; nt < 4; nt++)
                #pragma unroll
                for (int q = 0; q < 4; q++) {
                    int rg = wm * 64 + mt * 16 + (lane >> 2) + ((q >= 2) ? 8 : 0);
                    int cg = wn * 32 + nt * 8 + 2 * (lane & 3) + (q & 1);
                    if (rg == cg) g_diag[by * GM + rg] = acc[mt][nt][q];
                }
    }
    __syncthreads();
    if (t < 128) {
        atomicAdd(&g_rS1[by * GM + t], rS1[t]);
        atomicAdd(&g_rS2[by * GM + t], rS2[t]);
        atomicMax(&g_rM [by * GM + t], rMx[t]);
        atomicAdd(&g_cS1[bx * GN + t], cS1[t]);
        atomicAdd(&g_cS2[bx * GN + t], cS2[t]);
        atomicMax(&g_cM [bx * GN + t], cMx[t]);
    }
}

// ---------------------------------------------------------------------------
// K3: finalize — per-row/col losses from the statistics, then scalar reduce.
// ---------------------------------------------------------------------------
__global__ void __launch_bounds__(1024) k_final2(const float* __restrict__ sI,
                                                 const float* __restrict__ sT,
                                                 const float* __restrict__ bI,
                                                 const float* __restrict__ bT,
                                                 const int* __restrict__ ids,
                                                 float* __restrict__ out) {
    int t = threadIdx.x;
    float accI = 0.0f, accT = 0.0f;
    const float invB1 = 1.0f / (float)(Bq - 1);

    #pragma unroll
    for (int k = 0; k < Bq / 1024; k++) {
        int i = t + k * 1024;
        int id = ids[i];
        float diag = g_diag[i];
        float ed = __expf(10.0f * diag);

        // image (row i)
        {
            float M = __int_as_float(g_rM[i]) - 4.0f;
            float old_b = bI[id];
            float new_b = fmaxf(10.0f * (M - diag), old_b);
            float f = __expf(-10.0f * diag - new_b);
            float S1 = g_rS1[i], S2 = g_rS2[i];
            float se  = (S1 - ed) * f;
            float sed = (S2 - diag * S1) * f;
            float g = se * invB1;
            float sn = (1.0f - GAMMA_F) * sI[id] * __expf(old_b - new_b) + GAMMA_F * g;
            accI += sed / fmaxf(sn, EPS_F) * invB1;
        }
        // text (col i)
        {
            float M = __int_as_float(g_cM[i]) - 4.0f;
            float old_b = bT[id];
            float new_b = fmaxf(10.0f * (M - diag), old_b);
            float f = __expf(-10.0f * diag - new_b);
            float C1 = g_cS1[i], C2 = g_cS2[i];
            float se  = (C1 - ed) * f;
            float sed = (C2 - diag * C1) * f;
            float g = se * invB1;
            float sn = (1.0f - GAMMA_F) * sT[id] * __expf(old_b - new_b) + GAMMA_F * g;
            accT += sed / fmaxf(sn, EPS_F) * invB1;
        }
    }

    __shared__ float rI[1024];
    __shared__ float rT[1024];
    rI[t] = accI; rT[t] = accT;
    __syncthreads();
    #pragma unroll
    for (int s = 512; s > 0; s >>= 1) {
        if (t < s) { rI[t] += rI[t + s]; rT[t] += rT[t + s]; }
        __syncthreads();
    }
    if (t == 0)
        out[0] = ALPHA_F * (rI[0] / (float)Bq) + (1.0f - ALPHA_F) * (rT[0] / (float)Bq);
}

// ---------------------------------------------------------------------------
extern "C" void kernel_launch(void* const* d_in, const int* in_sizes, int n_in,
                              void* d_out, int out_size) {
    const float* zis = (const float*)d_in[0];
    const float* zjs = (const float*)d_in[1];
    const float* s_I = (const float*)d_in[2];
    const float* s_T = (const float*)d_in[3];
    const float* b_I = (const float*)d_in[4];
    const float* b_T = (const float*)d_in[5];
    const int*   ids = (const int*)d_in[6];

    cudaFuncSetAttribute(k_gemm_fused, cudaFuncAttributeMaxDynamicSharedMemorySize, GSMEM);

    k_zero<<<(Bq + 255) / 256, 256>>>();
    k_prep<<<2 * Bq, 256>>>(zis, zjs);
    dim3 g(Bq / GN, Bq / GM);
    k_gemm_fused<<<g, 256, GSMEM>>>();
    k_final2<<<1, 1024>>>(s_I, s_T, b_I, b_T, ids, (float*)d_out);
}